// round 9
// baseline (speedup 1.0000x reference)
#include <cuda_runtime.h>
#include <cuda_fp16.h>
#include <stdint.h>
#include <stddef.h>

#define TT 8192
#define HD 2048
#define FD 4096
#define NE 8
#define NSLOTS 17408          // 16384 assignments + worst-case 8*127 padding, rounded /128
#define MT_MAX 136            // NSLOTS/128
#define STAGES 4
#define STAGE_BYTES 32768     // A tile 16KB + B tile 16KB (128 rows x 64 halfs each)
#define SMEM_GEMM (STAGES*STAGE_BYTES)   // 131072

// ---------------- device scratch (no dynamic allocation allowed) ----------------
__device__ __half g_w1t[(size_t)NE*FD*HD];   // [e][f][h]  K-major
__device__ __half g_w3t[(size_t)NE*FD*HD];   // [e][f][h]
__device__ __half g_w2t[(size_t)NE*HD*FD];   // [e][h][f]  K-major
__device__ __half g_xg  [(size_t)NSLOTS*HD]; // gathered tokens fp16 (pads zeroed)
__device__ __half g_act1[(size_t)NSLOTS*FD]; // x@w1
__device__ __half g_act3[(size_t)NSLOTS*FD]; // x@w3
__device__ __half g_act [(size_t)NSLOTS*FD]; // silu(act1)*act3
__device__ float  g_y   [(size_t)NSLOTS*HD]; // ffn2 output per slot (fp32)
__device__ int    g_slot[TT*2];
__device__ int    g_tope[TT*2];
__device__ float  g_topw[TT*2];
__device__ int    g_cnt[NE];
__device__ int    g_cur[NE];
__device__ int    g_off[NE+1];

// ---------------- PTX helpers (sm_80-level; assemble on baseline sm_103) ----------------
__device__ __forceinline__ uint32_t smem_u32(const void* p){
    uint32_t a;
    asm("{ .reg .u64 t; cvta.to.shared.u64 t, %1; cvt.u32.u64 %0, t; }" : "=r"(a) : "l"(p));
    return a;
}
__device__ __forceinline__ uint32_t swz(uint32_t o){ return o ^ ((o >> 3) & 0x70); }
__device__ __forceinline__ void cp16(uint32_t s, const void* g){
    asm volatile("cp.async.cg.shared.global [%0], [%1], 16;" :: "r"(s), "l"(g));
}
__device__ __forceinline__ void cp_commit(){ asm volatile("cp.async.commit_group;" ::: "memory"); }
template<int N> __device__ __forceinline__ void cp_wait(){
    asm volatile("cp.async.wait_group %0;" :: "n"(N) : "memory");
}
__device__ __forceinline__ void ldsm4(uint32_t* r, uint32_t addr){
    asm volatile("ldmatrix.sync.aligned.m8n8.x4.shared.b16 {%0,%1,%2,%3}, [%4];"
        : "=r"(r[0]), "=r"(r[1]), "=r"(r[2]), "=r"(r[3]) : "r"(addr));
}
__device__ __forceinline__ void mma16816(float* d, const uint32_t* a, const uint32_t* b){
    asm volatile("mma.sync.aligned.m16n8k16.row.col.f32.f16.f16.f32 "
        "{%0,%1,%2,%3}, {%4,%5,%6,%7}, {%8,%9}, {%0,%1,%2,%3};"
        : "+f"(d[0]), "+f"(d[1]), "+f"(d[2]), "+f"(d[3])
        : "r"(a[0]), "r"(a[1]), "r"(a[2]), "r"(a[3]), "r"(b[0]), "r"(b[1]));
}

// Load one 128-row x 128-byte (64 half) K-slab, SW128-swizzled. g at slab origin, ldk in halfs.
__device__ __forceinline__ void load_tile(uint32_t sdst, const __half* g, int ldk, int tid){
    #pragma unroll
    for (int i = 0; i < 4; i++){
        int ch = tid + i*256;
        int r = ch >> 3, c = ch & 7;
        cp16(sdst + swz((uint32_t)((r << 7) + (c << 4))), g + (size_t)r*ldk + (c << 3));
    }
}

// ---------------- small kernels ----------------
__global__ void k_zero(){
    if (threadIdx.x < NE){ g_cnt[threadIdx.x] = 0; g_cur[threadIdx.x] = 0; }
}

// transpose-convert fp32 [R,C] -> fp16 [C,R], batched over E. which: 0=w1t 1=w3t 2=w2t
__global__ void k_transpose(const float* __restrict__ src, int R, int C, int which){
    __shared__ float t[32][33];
    __half* dstb = (which == 0) ? g_w1t : (which == 1) ? g_w3t : g_w2t;
    int e = blockIdx.z;
    const float* s = src + (size_t)e * R * C;
    __half* d = dstb + (size_t)e * R * C;
    int c0 = blockIdx.x * 32, r0 = blockIdx.y * 32;
    int tx = threadIdx.x, ty = threadIdx.y;
    #pragma unroll
    for (int j = 0; j < 32; j += 8)
        t[ty + j][tx] = s[(size_t)(r0 + ty + j) * C + c0 + tx];
    __syncthreads();
    #pragma unroll
    for (int j = 0; j < 32; j += 8)
        d[(size_t)(c0 + ty + j) * R + r0 + tx] = __float2half(t[tx][ty + j]);
}

__global__ void k_router(const float* __restrict__ x, const float* __restrict__ gw,
                         float* __restrict__ logits_out, int write_logits){
    int warp = (int)((blockIdx.x * blockDim.x + threadIdx.x) >> 5);
    int lane = threadIdx.x & 31;
    if (warp >= TT) return;
    const float* xr = x + (size_t)warp * HD;
    float acc[NE];
    #pragma unroll
    for (int e = 0; e < NE; e++) acc[e] = 0.f;
    for (int h = lane; h < HD; h += 32){
        float xv = xr[h];
        const float* g = gw + (size_t)h * NE;
        #pragma unroll
        for (int e = 0; e < NE; e++) acc[e] += xv * g[e];
    }
    #pragma unroll
    for (int e = 0; e < NE; e++)
        #pragma unroll
        for (int o = 16; o; o >>= 1) acc[e] += __shfl_xor_sync(0xFFFFFFFFu, acc[e], o);
    if (lane == 0){
        if (write_logits){
            #pragma unroll
            for (int e = 0; e < NE; e++) logits_out[(size_t)warp * NE + e] = acc[e];
        }
        int i1 = 0;
        #pragma unroll
        for (int e = 1; e < NE; e++) if (acc[e] > acc[i1]) i1 = e;
        int i2 = -1;
        #pragma unroll
        for (int e = 0; e < NE; e++){
            if (e == i1) continue;
            if (i2 < 0 || acc[e] > acc[i2]) i2 = e;
        }
        float t = expf(acc[i2] - acc[i1]);   // <= 1
        float p1 = 1.f / (1.f + t);
        float p2 = t * p1;
        g_tope[warp*2]   = i1;  g_tope[warp*2+1] = i2;
        g_topw[warp*2]   = p1;  g_topw[warp*2+1] = p2;
        atomicAdd(&g_cnt[i1], 1);
        atomicAdd(&g_cnt[i2], 1);
    }
}

__global__ void k_offsets(){
    if (threadIdx.x == 0 && blockIdx.x == 0){
        int acc = 0;
        for (int e = 0; e < NE; e++){
            g_off[e] = acc;
            acc += (g_cnt[e] + 127) & ~127;
        }
        g_off[NE] = acc;
    }
}

__global__ void k_gather(const float* __restrict__ x){
    int a = (int)((blockIdx.x * blockDim.x + threadIdx.x) >> 5);
    int lane = threadIdx.x & 31;
    if (a >= TT*2) return;
    int tok = a >> 1;
    int e = g_tope[a];
    int pos = 0;
    if (lane == 0){
        pos = g_off[e] + atomicAdd(&g_cur[e], 1);
        g_slot[a] = pos;
    }
    pos = __shfl_sync(0xFFFFFFFFu, pos, 0);
    const float4* src = (const float4*)(x + (size_t)tok * HD);
    __half2* dst = (__half2*)(g_xg + (size_t)pos * HD);
    #pragma unroll
    for (int i = lane; i < HD/4; i += 32){
        float4 v = src[i];
        dst[2*i]   = __floats2half2_rn(v.x, v.y);
        dst[2*i+1] = __floats2half2_rn(v.z, v.w);
    }
}

__global__ void k_padzero(){
    int b = blockIdx.x;          // NE * 128 blocks
    int e = b >> 7, r = b & 127;
    int row = g_off[e] + g_cnt[e] + r;
    if (row >= g_off[e+1]) return;
    uint4 z = {0u,0u,0u,0u};
    ((uint4*)(g_xg + (size_t)row * HD))[threadIdx.x] = z;  // 256 * 16B = 4KB row
}

// ---------------- grouped GEMM: C[128m x 128n] = A[m][K] @ B[n][K]^T ----------------
// All buffers are device globals selected at compile time (WHICH): never pass
// __device__ symbols from host code. 8 warps: 4m x 2n, warp tile 32x64.
// WHICH: 0 = x@w1t->act1 (K=HD,N=FD,f16)  1 = x@w3t->act3  2 = act@w2t->y (K=FD,N=HD,f32)
template<int WHICH>
__global__ void __launch_bounds__(256, 1) k_gemm(){
    constexpr int KDIM = (WHICH < 2) ? HD : FD;
    constexpr int NB   = (WHICH < 2) ? FD : HD;
    constexpr bool F32OUT = (WHICH == 2);

    extern __shared__ char smem[];
    uint32_t sb = smem_u32(smem);
    int tid = threadIdx.x, lane = tid & 31, wid = tid >> 5;

    int m0 = blockIdx.x * 128;
    if (m0 >= g_off[NE]) return;
    int e = 0;
    while (m0 >= g_off[e+1]) e++;
    int n0 = blockIdx.y * 128;

    const __half* A = (WHICH < 2) ? g_xg : g_act;
    const __half* B = (WHICH == 0) ? g_w1t : (WHICH == 1) ? g_w3t : g_w2t;

    const __half* Ag = A + (size_t)m0 * KDIM;
    const __half* Bg = B + (size_t)e * NB * KDIM + (size_t)n0 * KDIM;

    const int m_base = (wid & 3) * 32;
    const int n_base = (wid >> 2) * 64;
    // ldmatrix lane address components
    const int a_row  = m_base + (lane & 15);
    const int a_coff = (lane >> 4);                      // 0/1 -> k half-chunk
    const int b_row  = n_base + (lane & 7) + ((lane >> 4) << 3);
    const int b_coff = (lane >> 3) & 1;

    float acc[2][8][4];
    #pragma unroll
    for (int mt = 0; mt < 2; mt++)
        #pragma unroll
        for (int nt = 0; nt < 8; nt++)
            #pragma unroll
            for (int i = 0; i < 4; i++) acc[mt][nt][i] = 0.f;

    const int KT = KDIM / 64;
    #pragma unroll
    for (int p = 0; p < STAGES-1; p++){
        uint32_t st = sb + p * STAGE_BYTES;
        load_tile(st,         Ag + p*64, KDIM, tid);
        load_tile(st + 16384, Bg + p*64, KDIM, tid);
        cp_commit();
    }

    for (int ks = 0; ks < KT; ks++){
        cp_wait<STAGES-2>();
        __syncthreads();
        int kl = ks + STAGES - 1;
        if (kl < KT){
            uint32_t st = sb + (kl & (STAGES-1)) * STAGE_BYTES;
            load_tile(st,         Ag + kl*64, KDIM, tid);
            load_tile(st + 16384, Bg + kl*64, KDIM, tid);
        }
        cp_commit();   // empty commit keeps wait_group accounting aligned

        uint32_t As = sb + (ks & (STAGES-1)) * STAGE_BYTES;
        uint32_t Bs = As + 16384;
        #pragma unroll
        for (int kk = 0; kk < 4; kk++){
            uint32_t a[2][4], b[4][4];
            #pragma unroll
            for (int mt = 0; mt < 2; mt++)
                ldsm4(a[mt], As + swz((uint32_t)((a_row + mt*16) * 128 + (kk*2 + a_coff) * 16)));
            #pragma unroll
            for (int nq = 0; nq < 4; nq++)
                ldsm4(b[nq], Bs + swz((uint32_t)((b_row + nq*16) * 128 + (kk*2 + b_coff) * 16)));
            #pragma unroll
            for (int mt = 0; mt < 2; mt++)
                #pragma unroll
                for (int nt = 0; nt < 8; nt++)
                    mma16816(acc[mt][nt], a[mt], &b[nt >> 1][(nt & 1) * 2]);
        }
    }

    // epilogue: frag rows = lane/4 (+8), cols = 2*(lane%4)
    #pragma unroll
    for (int mt = 0; mt < 2; mt++){
        #pragma unroll
        for (int nt = 0; nt < 8; nt++){
            int m  = m_base + mt*16 + (lane >> 2);
            int nn = n0 + n_base + nt*8 + ((lane & 3) << 1);
            size_t r0 = (size_t)(m0 + m) * NB + nn;
            size_t r1 = (size_t)(m0 + m + 8) * NB + nn;
            if (F32OUT){
                g_y[r0] = acc[mt][nt][0]; g_y[r0+1] = acc[mt][nt][1];
                g_y[r1] = acc[mt][nt][2]; g_y[r1+1] = acc[mt][nt][3];
            } else {
                __half* Ch = (WHICH == 0) ? g_act1 : g_act3;
                *(__half2*)&Ch[r0] = __floats2half2_rn(acc[mt][nt][0], acc[mt][nt][1]);
                *(__half2*)&Ch[r1] = __floats2half2_rn(acc[mt][nt][2], acc[mt][nt][3]);
            }
        }
    }
}

__global__ void k_silu(){
    int row = blockIdx.x;
    if (row >= g_off[NE]) return;
    const __half2* p1 = (const __half2*)(g_act1 + (size_t)row * FD);
    const __half2* p3 = (const __half2*)(g_act3 + (size_t)row * FD);
    __half2* po = (__half2*)(g_act + (size_t)row * FD);
    for (int i = threadIdx.x; i < FD/2; i += 256){
        float2 a = __half22float2(p1[i]);
        float2 b = __half22float2(p3[i]);
        float s0 = a.x / (1.f + expf(-a.x)) * b.x;
        float s1 = a.y / (1.f + expf(-a.y)) * b.y;
        po[i] = __floats2half2_rn(s0, s1);
    }
}

__global__ void k_combine(float* __restrict__ out){
    int t = blockIdx.x;
    int s0 = g_slot[t*2], s1 = g_slot[t*2+1];
    float w0 = g_topw[t*2], w1 = g_topw[t*2+1];
    const float4* y0 = (const float4*)(g_y + (size_t)s0 * HD);
    const float4* y1 = (const float4*)(g_y + (size_t)s1 * HD);
    float4* o = (float4*)(out + (size_t)t * HD);
    for (int i = threadIdx.x; i < HD/4; i += 256){
        float4 a = y0[i], b = y1[i];
        o[i] = make_float4(w0*a.x + w1*b.x, w0*a.y + w1*b.y,
                           w0*a.z + w1*b.z, w0*a.w + w1*b.w);
    }
}

// ---------------- launch ----------------
extern "C" void kernel_launch(void* const* d_in, const int* in_sizes, int n_in,
                              void* d_out, int out_size){
    const float* x    = (const float*)d_in[0];
    const float* gate = (const float*)d_in[1];
    const float* w1   = (const float*)d_in[2];
    const float* w3   = (const float*)d_in[3];
    const float* w2   = (const float*)d_in[4];
    float* out = (float*)d_out;

    // router logits are output 1, appended after the TT*HD final output —
    // only write them if the harness actually allocated that region.
    int write_logits = (out_size >= TT*HD + TT*NE) ? 1 : 0;
    float* logits_out = out + (size_t)TT * HD;

    cudaFuncSetAttribute(k_gemm<0>, cudaFuncAttributeMaxDynamicSharedMemorySize, SMEM_GEMM);
    cudaFuncSetAttribute(k_gemm<1>, cudaFuncAttributeMaxDynamicSharedMemorySize, SMEM_GEMM);
    cudaFuncSetAttribute(k_gemm<2>, cudaFuncAttributeMaxDynamicSharedMemorySize, SMEM_GEMM);

    dim3 tb(32, 8);
    k_zero<<<1, 32>>>();
    k_transpose<<<dim3(FD/32, HD/32, NE), tb>>>(w1, HD, FD, 0);
    k_transpose<<<dim3(FD/32, HD/32, NE), tb>>>(w3, HD, FD, 1);
    k_transpose<<<dim3(HD/32, FD/32, NE), tb>>>(w2, FD, HD, 2);
    k_router<<<TT/8, 256>>>(x, gate, logits_out, write_logits);
    k_offsets<<<1, 32>>>();
    k_gather<<<(TT*2)/8, 256>>>(x);
    k_padzero<<<NE*128, 256>>>();

    // FFN1: act1 = x@w1^T, act3 = x@w3^T  (K=HD, N=FD, fp16 out)
    k_gemm<0><<<dim3(MT_MAX, FD/128), 256, SMEM_GEMM>>>();
    k_gemm<1><<<dim3(MT_MAX, FD/128), 256, SMEM_GEMM>>>();
    k_silu<<<NSLOTS, 256>>>();
    // FFN2: y = act@w2^T  (K=FD, N=HD, fp32 out)
    k_gemm<2><<<dim3(MT_MAX, HD/128), 256, SMEM_GEMM>>>();
    k_combine<<<TT, 256>>>(out);
}

// round 10
// speedup vs baseline: 1.2866x; 1.2866x over previous
#include <cuda_runtime.h>
#include <cuda_fp16.h>
#include <stdint.h>
#include <stddef.h>

#define TT 8192
#define HD 2048
#define FD 4096
#define NE 8
#define NSLOTS 17408          // 16384 assignments + worst-case 8*127 padding
#define MT_MAX 136            // NSLOTS/128
#define STAGES 3
#define STAGE_BYTES 32768     // FFN1: A 16KB + B1 8KB + B3 8KB ; FFN2: A 16KB + B 16KB
#define SMEM_GEMM (STAGES*STAGE_BYTES)   // 98304 -> 2 CTAs/SM

// ---------------- device scratch ----------------
__device__ __half g_w1t[(size_t)NE*FD*HD];   // [e][f][h]  K-major
__device__ __half g_w3t[(size_t)NE*FD*HD];
__device__ __half g_w2t[(size_t)NE*HD*FD];   // [e][h][f]  K-major
__device__ __half g_xg  [(size_t)NSLOTS*HD]; // gathered tokens fp16 (pads zeroed)
__device__ __half g_act [(size_t)NSLOTS*FD]; // silu(x@w1)*(x@w3)
__device__ float  g_y   [(size_t)NSLOTS*HD]; // ffn2 output per slot (fp32)
__device__ int    g_slot[TT*2];
__device__ int    g_tope[TT*2];
__device__ float  g_topw[TT*2];
__device__ int    g_cnt[NE];
__device__ int    g_cur[NE];
__device__ int    g_off[NE+1];

// ---------------- PTX helpers ----------------
__device__ __forceinline__ uint32_t smem_u32(const void* p){
    uint32_t a;
    asm("{ .reg .u64 t; cvta.to.shared.u64 t, %1; cvt.u32.u64 %0, t; }" : "=r"(a) : "l"(p));
    return a;
}
__device__ __forceinline__ uint32_t swz(uint32_t o){ return o ^ ((o >> 3) & 0x70); }
__device__ __forceinline__ void cp16(uint32_t s, const void* g){
    asm volatile("cp.async.cg.shared.global [%0], [%1], 16;" :: "r"(s), "l"(g));
}
__device__ __forceinline__ void cp_commit(){ asm volatile("cp.async.commit_group;" ::: "memory"); }
template<int N> __device__ __forceinline__ void cp_wait(){
    asm volatile("cp.async.wait_group %0;" :: "n"(N) : "memory");
}
__device__ __forceinline__ void ldsm4(uint32_t* r, uint32_t addr){
    asm volatile("ldmatrix.sync.aligned.m8n8.x4.shared.b16 {%0,%1,%2,%3}, [%4];"
        : "=r"(r[0]), "=r"(r[1]), "=r"(r[2]), "=r"(r[3]) : "r"(addr));
}
__device__ __forceinline__ void mma16816(float* d, const uint32_t* a, const uint32_t* b){
    asm volatile("mma.sync.aligned.m16n8k16.row.col.f32.f16.f16.f32 "
        "{%0,%1,%2,%3}, {%4,%5,%6,%7}, {%8,%9}, {%0,%1,%2,%3};"
        : "+f"(d[0]), "+f"(d[1]), "+f"(d[2]), "+f"(d[3])
        : "r"(a[0]), "r"(a[1]), "r"(a[2]), "r"(a[3]), "r"(b[0]), "r"(b[1]));
}

// Load one ROWS x 128-byte (64 half) K-slab, swizzled. 256 threads.
template<int ROWS>
__device__ __forceinline__ void load_tileR(uint32_t sdst, const __half* g, int ldk, int tid){
    #pragma unroll
    for (int i = 0; i < ROWS/32; i++){
        int ch = tid + i*256;
        int r = ch >> 3, c = ch & 7;
        cp16(sdst + swz((uint32_t)((r << 7) + (c << 4))), g + (size_t)r*ldk + (c << 3));
    }
}

// ---------------- small kernels ----------------
__global__ void k_zero(){
    if (threadIdx.x < NE){ g_cnt[threadIdx.x] = 0; g_cur[threadIdx.x] = 0; }
}

// transpose-convert fp32 [R,C] -> fp16 [C,R]; 64r x 32c tiles, half2 writes.
__global__ void k_transpose(const float* __restrict__ src, int R, int C, int which){
    __shared__ float s[32][65];   // s[c][r]
    __half* dstb = (which == 0) ? g_w1t : (which == 1) ? g_w3t : g_w2t;
    int e = blockIdx.z;
    const float* sp = src + (size_t)e * R * C;
    __half* d = dstb + (size_t)e * R * C;
    int c0 = blockIdx.x * 32, r0 = blockIdx.y * 64;
    int tx = threadIdx.x, ty = threadIdx.y;   // 32 x 8
    #pragma unroll
    for (int j = 0; j < 8; j++){
        int r = ty + j*8;
        s[tx][r] = sp[(size_t)(r0 + r) * C + c0 + tx];
    }
    __syncthreads();
    #pragma unroll
    for (int j = 0; j < 4; j++){
        int c = ty + j*8;
        __half2 v = __floats2half2_rn(s[c][2*tx], s[c][2*tx+1]);
        *(__half2*)&d[(size_t)(c0 + c) * R + r0 + 2*tx] = v;
    }
}

__global__ void k_router(const float* __restrict__ x, const float* __restrict__ gw,
                         float* __restrict__ logits_out, int write_logits){
    int warp = (int)((blockIdx.x * blockDim.x + threadIdx.x) >> 5);
    int lane = threadIdx.x & 31;
    if (warp >= TT) return;
    const float* xr = x + (size_t)warp * HD;
    float acc[NE];
    #pragma unroll
    for (int e = 0; e < NE; e++) acc[e] = 0.f;
    for (int h = lane; h < HD; h += 32){
        float xv = xr[h];
        const float* g = gw + (size_t)h * NE;
        #pragma unroll
        for (int e = 0; e < NE; e++) acc[e] += xv * g[e];
    }
    #pragma unroll
    for (int e = 0; e < NE; e++)
        #pragma unroll
        for (int o = 16; o; o >>= 1) acc[e] += __shfl_xor_sync(0xFFFFFFFFu, acc[e], o);
    if (lane == 0){
        if (write_logits){
            #pragma unroll
            for (int e = 0; e < NE; e++) logits_out[(size_t)warp * NE + e] = acc[e];
        }
        int i1 = 0;
        #pragma unroll
        for (int e = 1; e < NE; e++) if (acc[e] > acc[i1]) i1 = e;
        int i2 = -1;
        #pragma unroll
        for (int e = 0; e < NE; e++){
            if (e == i1) continue;
            if (i2 < 0 || acc[e] > acc[i2]) i2 = e;
        }
        float t = expf(acc[i2] - acc[i1]);
        float p1 = 1.f / (1.f + t);
        float p2 = t * p1;
        g_tope[warp*2]   = i1;  g_tope[warp*2+1] = i2;
        g_topw[warp*2]   = p1;  g_topw[warp*2+1] = p2;
        atomicAdd(&g_cnt[i1], 1);
        atomicAdd(&g_cnt[i2], 1);
    }
}

__global__ void k_offsets(){
    if (threadIdx.x == 0 && blockIdx.x == 0){
        int acc = 0;
        for (int e = 0; e < NE; e++){
            g_off[e] = acc;
            acc += (g_cnt[e] + 127) & ~127;
        }
        g_off[NE] = acc;
    }
}

__global__ void k_gather(const float* __restrict__ x){
    int a = (int)((blockIdx.x * blockDim.x + threadIdx.x) >> 5);
    int lane = threadIdx.x & 31;
    if (a >= TT*2) return;
    int tok = a >> 1;
    int e = g_tope[a];
    int pos = 0;
    if (lane == 0){
        pos = g_off[e] + atomicAdd(&g_cur[e], 1);
        g_slot[a] = pos;
    }
    pos = __shfl_sync(0xFFFFFFFFu, pos, 0);
    const float4* src = (const float4*)(x + (size_t)tok * HD);
    __half2* dst = (__half2*)(g_xg + (size_t)pos * HD);
    #pragma unroll
    for (int i = lane; i < HD/4; i += 32){
        float4 v = src[i];
        dst[2*i]   = __floats2half2_rn(v.x, v.y);
        dst[2*i+1] = __floats2half2_rn(v.z, v.w);
    }
}

__global__ void k_padzero(){
    int b = blockIdx.x;
    int e = b >> 7, r = b & 127;
    int row = g_off[e] + g_cnt[e] + r;
    if (row >= g_off[e+1]) return;
    uint4 z = {0u,0u,0u,0u};
    ((uint4*)(g_xg + (size_t)row * HD))[threadIdx.x] = z;
}

// ---------------- FFN1 fused: g_act = silu(x@w1^T) * (x@w3^T) ----------------
// Block tile M=128, N=64 (per matrix). 8 warps 4m x 2n; warp tile 32x32 per matrix.
__global__ void __launch_bounds__(256, 2) k_ffn1(){
    extern __shared__ char smem[];
    uint32_t sb = smem_u32(smem);
    int tid = threadIdx.x, lane = tid & 31, wid = tid >> 5;

    int m0 = blockIdx.x * 128;
    if (m0 >= g_off[NE]) return;
    int e = 0;
    while (m0 >= g_off[e+1]) e++;
    int n0 = blockIdx.y * 64;

    const __half* Ag  = g_xg  + (size_t)m0 * HD;
    const __half* B1g = g_w1t + (size_t)e * FD * HD + (size_t)n0 * HD;
    const __half* B3g = g_w3t + (size_t)e * FD * HD + (size_t)n0 * HD;

    const int m_base = (wid & 3) * 32;
    const int n_base = (wid >> 2) * 32;
    const int a_row  = m_base + (lane & 15);
    const int a_coff = (lane >> 4);
    const int b_row  = n_base + (lane & 7) + ((lane >> 4) << 3);
    const int b_coff = (lane >> 3) & 1;

    float acc1[2][4][4], acc3[2][4][4];
    #pragma unroll
    for (int mt = 0; mt < 2; mt++)
        #pragma unroll
        for (int nt = 0; nt < 4; nt++)
            #pragma unroll
            for (int i = 0; i < 4; i++){ acc1[mt][nt][i] = 0.f; acc3[mt][nt][i] = 0.f; }

    const int KT = HD / 64;   // 32
    #pragma unroll
    for (int p = 0; p < STAGES-1; p++){
        uint32_t st = sb + p * STAGE_BYTES;
        load_tileR<128>(st,         Ag  + p*64, HD, tid);
        load_tileR<64> (st + 16384, B1g + p*64, HD, tid);
        load_tileR<64> (st + 24576, B3g + p*64, HD, tid);
        cp_commit();
    }

    int sc = 0, sl = STAGES-1;
    for (int ks = 0; ks < KT; ks++){
        cp_wait<STAGES-2>();
        __syncthreads();
        int kl = ks + STAGES - 1;
        if (kl < KT){
            uint32_t st = sb + sl * STAGE_BYTES;
            load_tileR<128>(st,         Ag  + kl*64, HD, tid);
            load_tileR<64> (st + 16384, B1g + kl*64, HD, tid);
            load_tileR<64> (st + 24576, B3g + kl*64, HD, tid);
        }
        cp_commit();

        uint32_t As  = sb + sc * STAGE_BYTES;
        uint32_t B1s = As + 16384, B3s = As + 24576;
        #pragma unroll
        for (int kk = 0; kk < 4; kk++){
            uint32_t a[2][4], b1[2][4], b3[2][4];
            #pragma unroll
            for (int mt = 0; mt < 2; mt++)
                ldsm4(a[mt], As + swz((uint32_t)((a_row + mt*16) * 128 + (kk*2 + a_coff) * 16)));
            #pragma unroll
            for (int nq = 0; nq < 2; nq++){
                ldsm4(b1[nq], B1s + swz((uint32_t)((b_row + nq*16) * 128 + (kk*2 + b_coff) * 16)));
                ldsm4(b3[nq], B3s + swz((uint32_t)((b_row + nq*16) * 128 + (kk*2 + b_coff) * 16)));
            }
            #pragma unroll
            for (int mt = 0; mt < 2; mt++)
                #pragma unroll
                for (int nt = 0; nt < 4; nt++){
                    mma16816(acc1[mt][nt], a[mt], &b1[nt >> 1][(nt & 1) * 2]);
                    mma16816(acc3[mt][nt], a[mt], &b3[nt >> 1][(nt & 1) * 2]);
                }
        }
        sc = (sc == STAGES-1) ? 0 : sc+1;
        sl = (sl == STAGES-1) ? 0 : sl+1;
    }

    // fused silu epilogue
    #pragma unroll
    for (int mt = 0; mt < 2; mt++){
        #pragma unroll
        for (int nt = 0; nt < 4; nt++){
            int m  = m0 + m_base + mt*16 + (lane >> 2);
            int nn = n0 + n_base + nt*8 + ((lane & 3) << 1);
            #pragma unroll
            for (int h = 0; h < 2; h++){
                float a0 = acc1[mt][nt][2*h],   a1 = acc1[mt][nt][2*h+1];
                float b0 = acc3[mt][nt][2*h],   b1 = acc3[mt][nt][2*h+1];
                float s0 = a0 / (1.f + expf(-a0)) * b0;
                float s1 = a1 / (1.f + expf(-a1)) * b1;
                *(__half2*)&g_act[(size_t)(m + 8*h) * FD + nn] = __floats2half2_rn(s0, s1);
            }
        }
    }
}

// ---------------- FFN2: g_y = act @ w2^T  (K=FD, N=HD, fp32 out) ----------------
__global__ void __launch_bounds__(256, 2) k_ffn2(){
    extern __shared__ char smem[];
    uint32_t sb = smem_u32(smem);
    int tid = threadIdx.x, lane = tid & 31, wid = tid >> 5;

    int m0 = blockIdx.x * 128;
    if (m0 >= g_off[NE]) return;
    int e = 0;
    while (m0 >= g_off[e+1]) e++;
    int n0 = blockIdx.y * 128;

    const __half* Ag = g_act + (size_t)m0 * FD;
    const __half* Bg = g_w2t + (size_t)e * HD * FD + (size_t)n0 * FD;

    const int m_base = (wid & 3) * 32;
    const int n_base = (wid >> 2) * 64;
    const int a_row  = m_base + (lane & 15);
    const int a_coff = (lane >> 4);
    const int b_row  = n_base + (lane & 7) + ((lane >> 4) << 3);
    const int b_coff = (lane >> 3) & 1;

    float acc[2][8][4];
    #pragma unroll
    for (int mt = 0; mt < 2; mt++)
        #pragma unroll
        for (int nt = 0; nt < 8; nt++)
            #pragma unroll
            for (int i = 0; i < 4; i++) acc[mt][nt][i] = 0.f;

    const int KT = FD / 64;   // 64
    #pragma unroll
    for (int p = 0; p < STAGES-1; p++){
        uint32_t st = sb + p * STAGE_BYTES;
        load_tileR<128>(st,         Ag + p*64, FD, tid);
        load_tileR<128>(st + 16384, Bg + p*64, FD, tid);
        cp_commit();
    }

    int sc = 0, sl = STAGES-1;
    for (int ks = 0; ks < KT; ks++){
        cp_wait<STAGES-2>();
        __syncthreads();
        int kl = ks + STAGES - 1;
        if (kl < KT){
            uint32_t st = sb + sl * STAGE_BYTES;
            load_tileR<128>(st,         Ag + kl*64, FD, tid);
            load_tileR<128>(st + 16384, Bg + kl*64, FD, tid);
        }
        cp_commit();

        uint32_t As = sb + sc * STAGE_BYTES;
        uint32_t Bs = As + 16384;
        #pragma unroll
        for (int kk = 0; kk < 4; kk++){
            uint32_t a[2][4], b[4][4];
            #pragma unroll
            for (int mt = 0; mt < 2; mt++)
                ldsm4(a[mt], As + swz((uint32_t)((a_row + mt*16) * 128 + (kk*2 + a_coff) * 16)));
            #pragma unroll
            for (int nq = 0; nq < 4; nq++)
                ldsm4(b[nq], Bs + swz((uint32_t)((b_row + nq*16) * 128 + (kk*2 + b_coff) * 16)));
            #pragma unroll
            for (int mt = 0; mt < 2; mt++)
                #pragma unroll
                for (int nt = 0; nt < 8; nt++)
                    mma16816(acc[mt][nt], a[mt], &b[nt >> 1][(nt & 1) * 2]);
        }
        sc = (sc == STAGES-1) ? 0 : sc+1;
        sl = (sl == STAGES-1) ? 0 : sl+1;
    }

    #pragma unroll
    for (int mt = 0; mt < 2; mt++){
        #pragma unroll
        for (int nt = 0; nt < 8; nt++){
            int m  = m0 + m_base + mt*16 + (lane >> 2);
            int nn = n0 + n_base + nt*8 + ((lane & 3) << 1);
            size_t r0 = (size_t)m * HD + nn;
            size_t r1 = (size_t)(m + 8) * HD + nn;
            g_y[r0] = acc[mt][nt][0]; g_y[r0+1] = acc[mt][nt][1];
            g_y[r1] = acc[mt][nt][2]; g_y[r1+1] = acc[mt][nt][3];
        }
    }
}

__global__ void k_combine(float* __restrict__ out){
    int t = blockIdx.x;
    int s0 = g_slot[t*2], s1 = g_slot[t*2+1];
    float w0 = g_topw[t*2], w1 = g_topw[t*2+1];
    const float4* y0 = (const float4*)(g_y + (size_t)s0 * HD);
    const float4* y1 = (const float4*)(g_y + (size_t)s1 * HD);
    float4* o = (float4*)(out + (size_t)t * HD);
    for (int i = threadIdx.x; i < HD/4; i += 256){
        float4 a = y0[i], b = y1[i];
        o[i] = make_float4(w0*a.x + w1*b.x, w0*a.y + w1*b.y,
                           w0*a.z + w1*b.z, w0*a.w + w1*b.w);
    }
}

// ---------------- launch ----------------
extern "C" void kernel_launch(void* const* d_in, const int* in_sizes, int n_in,
                              void* d_out, int out_size){
    const float* x    = (const float*)d_in[0];
    const float* gate = (const float*)d_in[1];
    const float* w1   = (const float*)d_in[2];
    const float* w3   = (const float*)d_in[3];
    const float* w2   = (const float*)d_in[4];
    float* out = (float*)d_out;

    int write_logits = (out_size >= TT*HD + TT*NE) ? 1 : 0;
    float* logits_out = out + (size_t)TT * HD;

    cudaFuncSetAttribute(k_ffn1, cudaFuncAttributeMaxDynamicSharedMemorySize, SMEM_GEMM);
    cudaFuncSetAttribute(k_ffn2, cudaFuncAttributeMaxDynamicSharedMemorySize, SMEM_GEMM);

    dim3 tb(32, 8);
    k_zero<<<1, 32>>>();
    k_transpose<<<dim3(FD/32, HD/64, NE), tb>>>(w1, HD, FD, 0);
    k_transpose<<<dim3(FD/32, HD/64, NE), tb>>>(w3, HD, FD, 1);
    k_transpose<<<dim3(HD/32, FD/64, NE), tb>>>(w2, FD, HD, 2);
    k_router<<<TT/8, 256>>>(x, gate, logits_out, write_logits);
    k_offsets<<<1, 32>>>();
    k_gather<<<(TT*2)/8, 256>>>(x);
    k_padzero<<<NE*128, 256>>>();

    k_ffn1<<<dim3(MT_MAX, FD/64), 256, SMEM_GEMM>>>();
    k_ffn2<<<dim3(MT_MAX, HD/128), 256, SMEM_GEMM>>>();
    k_combine<<<TT, 256>>>(out);
}